// round 4
// baseline (speedup 1.0000x reference)
#include <cuda_runtime.h>
#include <cuda_bf16.h>

// NDFT type-2: y[b,m] = sum_{k1,k2=-32..31} f_hat[b,k1+32,k2+32]
//                        * exp(-2*pi*i*(k1*x1 + k2*x2))
//
// Radix factorization of k2: k2 = 16a + c - 32, a in [0,4), c in [0,16)
//   e2[k2] = E2c[a] * E2f[c]
//   y = sum_c E2f[c] * S[c],  S[c] = sum_{k1,a} f[k1,16a+c] * (e1[k1]*E2c[a])
//
// Block = 128 threads = 4 warps; each lane = one sample point (32 pts/block),
// each warp owns 16 k1 rows. All shared loads are 32-lane broadcasts
// (conflict-free). S[c] accumulated with packed fma.rn.f32x2 (c-pairs);
// g twiddle also computed packed. Cross-warp combine via smem.

#define B_DIM 2
#define M_DIM 8192
#define N1 64
#define N2 64
#define K_TOT (N1 * N2)
#define TPB 128
#define NWARP 4
#define PTS 32                               // points per block
#define ROWS_PW (N1 / NWARP)                 // 16 k1 rows per warp
#define BLOCKS_PER_B (M_DIM / PTS)           // 256

typedef unsigned long long ull;

#define PACK2(d, lo, hi) \
    asm("mov.b64 %0, {%1, %2};" : "=l"(d) \
        : "r"(__float_as_uint(lo)), "r"(__float_as_uint(hi)))
#define FMA2(d, a, b, c) \
    asm("fma.rn.f32x2 %0, %1, %2, %3;" : "=l"(d) : "l"(a), "l"(b), "l"(c))
#define MUL2(d, a, b) \
    asm("mul.rn.f32x2 %0, %1, %2;" : "=l"(d) : "l"(a), "l"(b))
#define UNPACK2(lo, hi, s) do { unsigned int _l, _h; \
    asm("mov.b64 {%0, %1}, %2;" : "=r"(_l), "=r"(_h) : "l"(s)); \
    (lo) = __uint_as_float(_l); (hi) = __uint_as_float(_h); } while (0)

__global__ __launch_bounds__(TPB) void ndft_kernel(
    const float* __restrict__ x,      // [B, M, 2]
    const float* __restrict__ f_hat,  // [B, 64, 64]
    float* __restrict__ out,
    const int real_only)
{
    __shared__ __align__(16) float sf[K_TOT];    // 16 KB coefficients
    __shared__ float2 sy[NWARP][PTS];            // per-warp partial results

    const int b    = blockIdx.x / BLOCKS_PER_B;
    const int mblk = blockIdx.x % BLOCKS_PER_B;
    const int tid  = threadIdx.x;
    const int w    = tid >> 5;                   // warp id: k1 chunk
    const int lane = tid & 31;
    const int m    = mblk * PTS + lane;          // this lane's point

    // cooperative load of f_hat[b] into shared
    {
        const float4* src = reinterpret_cast<const float4*>(f_hat + b * K_TOT);
        float4* dst = reinterpret_cast<float4*>(sf);
        #pragma unroll
        for (int i = tid; i < K_TOT / 4; i += TPB)
            dst[i] = src[i];
    }
    __syncthreads();

    const float2 xv = reinterpret_cast<const float2*>(x)[b * M_DIM + m];
    const float x1 = xv.x, x2 = xv.y;

    // ---- twiddles (sincospif: arg in units of pi, exact range reduction) ----
    float w1r, w1i;                   // w1 = exp(-2*pi*i*x1)
    sincospif(-2.0f * x1, &w1i, &w1r);
    // e1 anchor for this warp: k1start = 16*w - 32 -> angle/pi = (64 - 32*w)*x1
    float e1r, e1i;
    sincospif((64.0f - 32.0f * (float)w) * x1, &e1i, &e1r);
    float w2r, w2i;                   // w2 = exp(-2*pi*i*x2)
    sincospif(-2.0f * x2, &w2i, &w2r);
    float W16r, W16i;                 // W16 = w2^16 = exp(-32*pi*i*x2)
    sincospif(-32.0f * x2, &W16i, &W16r);
    float C0r, C0i;                   // E2c[0] = exp(-2*pi*i*(-32)*x2)
    sincospif(64.0f * x2, &C0i, &C0r);

    // E2c[a] = C0 * W16^a, a in [0,4): packed splats (crr, cii) per a
    ull crr[4], cii[4];
    {
        float cr = C0r, ci = C0i;
        #pragma unroll
        for (int a = 0; a < 4; ++a) {
            PACK2(crr[a], cr, cr);
            PACK2(cii[a], ci, ci);
            const float t = cr * W16r - ci * W16i;
            ci = cr * W16i + ci * W16r;
            cr = t;
        }
    }

    // packed accumulators over c in [0,16): pair p holds (c=2p, c=2p+1)
    ull sr2[8], si2[8];
    #pragma unroll
    for (int p = 0; p < 8; ++p) { sr2[p] = 0ull; si2[p] = 0ull; }

    #pragma unroll 1
    for (int i1 = 0; i1 < ROWS_PW; ++i1) {
        const int row = w * ROWS_PW + i1;
        const ulonglong2* frow =
            reinterpret_cast<const ulonglong2*>(sf + row * N2);

        ull e1rr, e1ii, e1nii;
        PACK2(e1rr, e1r, e1r);
        PACK2(e1ii, e1i, e1i);
        PACK2(e1nii, -e1i, -e1i);

        #pragma unroll
        for (int a = 0; a < 4; ++a) {
            // g = e1 * E2c[a], packed splat
            ull grr, gii, t0, t1;
            MUL2(t0, e1rr, crr[a]);
            FMA2(grr, e1nii, cii[a], t0);   // gr = e1r*cr - e1i*ci
            MUL2(t1, e1rr, cii[a]);
            FMA2(gii, e1ii, crr[a], t1);    // gi = e1r*ci + e1i*cr

            #pragma unroll
            for (int j = 0; j < 4; ++j) {
                // f[row, 16a + 4j .. 16a + 4j + 3]: one broadcast LDS.128
                const ulonglong2 f = frow[a * 4 + j];
                FMA2(sr2[2*j],   f.x, grr, sr2[2*j]);
                FMA2(si2[2*j],   f.x, gii, si2[2*j]);
                FMA2(sr2[2*j+1], f.y, grr, sr2[2*j+1]);
                FMA2(si2[2*j+1], f.y, gii, si2[2*j+1]);
            }
        }

        // e1 *= w1  (16-step chain, anchored by sincospif per warp)
        const float t = e1r * w1r - e1i * w1i;
        e1i = e1r * w1i + e1i * w1r;
        e1r = t;
    }

    // ---- tail: y_partial = sum_c E2f[c] * S[c],  E2f[c] = w2^c ----
    float yr = 0.0f, yi = 0.0f;
    {
        float fr = 1.0f, fi = 0.0f;   // E2f[c] recurrence
        #pragma unroll
        for (int c = 0; c < 16; ++c) {
            float s_r, s_i, dum;
            if (c & 1) { UNPACK2(dum, s_r, sr2[c >> 1]); UNPACK2(dum, s_i, si2[c >> 1]); }
            else       { UNPACK2(s_r, dum, sr2[c >> 1]); UNPACK2(s_i, dum, si2[c >> 1]); }
            yr += fr * s_r - fi * s_i;
            yi += fr * s_i + fi * s_r;
            const float t = fr * w2r - fi * w2i;
            fi = fr * w2i + fi * w2r;
            fr = t;
        }
    }

    // ---- cross-warp reduction ----
    sy[w][lane] = make_float2(yr, yi);
    __syncthreads();

    if (tid < PTS) {
        float2 acc = sy[0][tid];
        #pragma unroll
        for (int ww = 1; ww < NWARP; ++ww) {
            acc.x += sy[ww][tid].x;
            acc.y += sy[ww][tid].y;
        }
        const int mo = mblk * PTS + tid;
        if (real_only) {
            out[b * M_DIM + mo] = acc.x;
        } else {
            reinterpret_cast<float2*>(out)[b * M_DIM + mo] = acc;
        }
    }
}

extern "C" void kernel_launch(void* const* d_in, const int* in_sizes, int n_in,
                              void* d_out, int out_size) {
    // Select inputs by element count (metadata order may differ):
    //   x: 2*8192*2 = 32768, f_hat: 2*64*64 = 8192
    const float* x;
    const float* f_hat;
    if (in_sizes[0] == B_DIM * M_DIM * 2) {
        x = (const float*)d_in[0];
        f_hat = (const float*)d_in[1];
    } else {
        x = (const float*)d_in[1];
        f_hat = (const float*)d_in[0];
    }

    float* out = (float*)d_out;
    const int real_only = (out_size == B_DIM * M_DIM) ? 1 : 0;

    ndft_kernel<<<B_DIM * BLOCKS_PER_B, TPB>>>(x, f_hat, out, real_only);
}